// round 17
// baseline (speedup 1.0000x reference)
#include <cuda_runtime.h>
#include <cuda_fp16.h>
#include <cstdint>

#define Bb 4
#define Nn 4096
#define Dd 256
#define Mm (Bb*Nn)

__device__ __half g_Q16[Mm*Dd], g_K16[Mm*Dd], g_V16[Mm*Dd];

// ---------------- mma.sync / ldmatrix / cp.async ----------------
__device__ __forceinline__ uint32_t smem_u32(const void* p)
{ uint32_t a;
  asm("{ .reg .u64 t; cvta.to.shared.u64 t, %1; cvt.u32.u64 %0, t; }":"=r"(a):"l"(p));
  return a; }

__device__ __forceinline__ void ldsm4(uint32_t* r, uint32_t a)
{ asm volatile("ldmatrix.sync.aligned.m8n8.x4.shared.b16 {%0,%1,%2,%3}, [%4];"
    : "=r"(r[0]), "=r"(r[1]), "=r"(r[2]), "=r"(r[3]) : "r"(a)); }
__device__ __forceinline__ void ldsm4t(uint32_t* r, uint32_t a)
{ asm volatile("ldmatrix.sync.aligned.m8n8.x4.trans.shared.b16 {%0,%1,%2,%3}, [%4];"
    : "=r"(r[0]), "=r"(r[1]), "=r"(r[2]), "=r"(r[3]) : "r"(a)); }

// fp16 MMA
__device__ __forceinline__ void mma16816h(float* c, const uint32_t* a, const uint32_t* b)
{ asm volatile("mma.sync.aligned.m16n8k16.row.col.f32.f16.f16.f32 "
    "{%0,%1,%2,%3}, {%4,%5,%6,%7}, {%8,%9}, {%0,%1,%2,%3};"
    : "+f"(c[0]), "+f"(c[1]), "+f"(c[2]), "+f"(c[3])
    : "r"(a[0]), "r"(a[1]), "r"(a[2]), "r"(a[3]), "r"(b[0]), "r"(b[1])); }

#define CPA16(d, s) asm volatile("cp.async.cg.shared.global [%0], [%1], 16;"::"r"(d),"l"(s))
#define CPCOMMIT()  asm volatile("cp.async.commit_group;":::"memory")
#define CPWAIT0()   asm volatile("cp.async.wait_group 0;":::"memory")

// swizzled blocked-atom layouts (Swizzle<3,4,3>, 128B rows)
#define SWZ(o) ((o) ^ (((o) >> 3) & 0x70))
__device__ __forceinline__ uint32_t xswz(int r, int cb)   // 128 rows x 512B
{ return SWZ((uint32_t)((((r>>3) + (cb>>7)*16)*1024) + (r&7)*128 + (cb&127))); }
__device__ __forceinline__ uint32_t qswz(int r, int cb)   // 64 rows x 512B
{ return SWZ((uint32_t)((((r>>3) + (cb>>7)*8)*1024) + (r&7)*128 + (cb&127))); }
__device__ __forceinline__ uint32_t kswz(int r, int cb)   // 32 rows x 512B
{ return SWZ((uint32_t)((((r>>3) + (cb>>7)*4)*1024) + (r&7)*128 + (cb&127))); }
__device__ __forceinline__ uint32_t pswz(int r, int cb)   // 128B rows
{ return SWZ((uint32_t)(r*128 + cb)); }

__device__ __forceinline__ uint32_t packh2(float a, float b)
{ return (uint32_t)__half_as_ushort(__float2half_rn(a))
       | ((uint32_t)__half_as_ushort(__float2half_rn(b)) << 16); }

// attention SMEM map (fp16): Q 32K | K 2x16K | V 2x16K | P 2x8K
#define SM_Q  0
#define SM_K  32768
#define SM_V  65536
#define SM_P  98304
#define SM_TOT_A 114688

// qkvmm SMEM map (fp16 staged)
#define SMX 0
#define SMW 65536
#define SM_QKV_TOT 98304

// ---------------------------------------------------------------------------
// qkvmm: fp16 HMMA QKV projection, reads fp32 x/W and converts while staging.
// CTA = 128 m-rows x 256 e (4 e-tiles), 8 warps (warp = 16 rows x 64 e).
// ---------------------------------------------------------------------------
__global__ __launch_bounds__(256, 1)
void qkvmm_kernel(const float* __restrict__ x,
                  const float* __restrict__ Wq, const float* __restrict__ Wk,
                  const float* __restrict__ Wv,
                  const float* __restrict__ bq, const float* __restrict__ bk,
                  const float* __restrict__ bv)
{
    extern __shared__ char sm[];
    uint32_t sb = smem_u32(sm);
    const int t = threadIdx.x, lane = t & 31, wid = t >> 5;
    const int z = blockIdx.x;
    const int m0 = blockIdx.y * 128;
    const float* bias = (z == 0) ? bq : (z == 1) ? bk : bv;
    const float* Wz   = (z == 0) ? Wq : (z == 1) ? Wk : Wv;
    __half* o16 = (z == 0) ? g_Q16 : (z == 1) ? g_K16 : g_V16;
    const float* xp = x + (size_t)m0 * Dd;

    // stage x tile (128 x 256 fp32 -> fp16, swizzled): 8192 float4 chunks
    #pragma unroll
    for (int i = 0; i < 32; i++) {
        int id = i*256 + t;
        int row = id >> 6, c4 = id & 63;
        float4 v = *(const float4*)(xp + (size_t)row*Dd + c4*4);
        *(uint2*)(sm + SMX + xswz(row, c4*8)) =
            make_uint2(packh2(v.x, v.y), packh2(v.z, v.w));
    }

    const int lrow = lane & 15, lk16 = (lane >> 4) * 16;
    const int wrow = (lane >> 4) * 8 + (lane & 7);
    const int kb16 = ((lane >> 3) & 1) * 16;
    const int g = lane >> 2, tq = lane & 3;

    for (int et = 0; et < 4; et++) {
        __syncthreads();
        // stage W tile (64 x 256 fp32 -> fp16, swizzled): 4096 chunks
        const float* wph = Wz + (size_t)et * 64 * Dd;
        #pragma unroll
        for (int i = 0; i < 16; i++) {
            int id = i*256 + t;
            int row = id >> 6, c4 = id & 63;
            float4 v = *(const float4*)(wph + (size_t)row*Dd + c4*4);
            *(uint2*)(sm + SMW + qswz(row, c4*8)) =
                make_uint2(packh2(v.x, v.y), packh2(v.z, v.w));
        }
        __syncthreads();

        float acc[8][4] = {};
        #pragma unroll
        for (int ks = 0; ks < 16; ks++) {
            uint32_t ax[4];
            ldsm4(ax, sb + SMX + xswz(16*wid + lrow, ks*32 + lk16));
            #pragma unroll
            for (int n16 = 0; n16 < 4; n16++) {
                uint32_t bw[4];
                ldsm4(bw, sb + SMW + qswz(n16*16 + wrow, ks*32 + kb16));
                mma16816h(acc[n16*2],   ax, bw);
                mma16816h(acc[n16*2+1], ax, bw + 2);
            }
        }

        size_t row0 = (size_t)(m0 + 16*wid + g);
        #pragma unroll
        for (int n2 = 0; n2 < 8; n2++) {
            int col = et*64 + n2*8 + 2*tq;
            float b0 = bias[col], b1 = bias[col + 1];
            *(uint32_t*)&o16[row0*Dd + col] =
                packh2(acc[n2][0] + b0, acc[n2][1] + b1);
            *(uint32_t*)&o16[(row0 + 8)*Dd + col] =
                packh2(acc[n2][2] + b0, acc[n2][3] + b1);
        }
    }
}

// ---------------------------------------------------------------------------
// fp16 HMMA flash attention (byte-identical to R16 — known good, 326 µs):
// MMA-level S/PV interleave, 4-way split S accumulators, persistent Q regs.
// ---------------------------------------------------------------------------
__global__ __launch_bounds__(256, 1)
void attn_kernel(const int* __restrict__ mask, float* __restrict__ out)
{
    extern __shared__ char sm[];
    uint32_t sb = smem_u32(sm);
    const int t = threadIdx.x, lane = t & 31, wid = t >> 5;
    const int r = wid & 3, cw = wid >> 2;
    const int b = blockIdx.y, q0 = blockIdx.x * 64;
    const int g = lane >> 2, tq = lane & 3;
    const int lrow = lane & 15, lk16 = (lane >> 4) * 16;

    // Q fp16 -> smem (blocked swizzled)
    {
        const char* q16 = (const char*)&g_Q16[(size_t)(b*Nn + q0)*Dd];
        #pragma unroll
        for (int i = 0; i < 8; i++) {
            int id = i*256 + t;
            int row = id >> 5, cb = (id & 31) * 16;
            *(uint4*)(sm + SM_Q + qswz(row, cb)) =
                *(const uint4*)(q16 + (size_t)row*512 + cb);
        }
    }

    const char* baseK = (const char*)&g_K16[(size_t)(b*Nn)*Dd];
    const char* baseV = (const char*)&g_V16[(size_t)(b*Nn)*Dd];

    // prologue: K(0) into K stage 0
    #pragma unroll
    for (int i = 0; i < 4; i++) {
        int id = i*256 + t;
        int row = id >> 5, cb = (id & 31) * 16;
        CPA16(sb + SM_K + kswz(row, cb), baseK + (size_t)row*512 + cb);
    }
    CPCOMMIT();

    __syncthreads();   // Q smem visible

    // persistent Q fragments
    uint32_t qf[16][4];
    #pragma unroll
    for (int ks = 0; ks < 16; ks++)
        ldsm4(qf[ks], sb + SM_Q + qswz(16*r + lrow, ks*32 + lk16));

    float l0 = 0.f, l1 = 0.f;
    float o[16][4];
    #pragma unroll
    for (int i = 0; i < 16; i++)
        { o[i][0] = 0.f; o[i][1] = 0.f; o[i][2] = 0.f; o[i][3] = 0.f; }

    const int key  = 16*cw + (lane >> 4)*8 + (lane & 7);
    const int kb16 = ((lane >> 3) & 1) * 16;
    const int vr   = (lane & 7) + ((lane >> 3) & 1) * 8;

    for (int j = 0; j <= 128; j++) {
        CPWAIT0();
        __syncthreads();   // K(j), V(j-1), P(j-1) visible; old buffers free

        // issue K(j+1) -> stage (j+1)&1, V(j) -> stage j&1
        if (j + 1 <= 127) {
            uint32_t dst = sb + SM_K + ((j+1)&1)*16384;
            size_t gb = (size_t)(j+1)*16384;
            #pragma unroll
            for (int i = 0; i < 4; i++) {
                int id = i*256 + t;
                int row = id >> 5, cb = (id & 31) * 16;
                CPA16(dst + kswz(row, cb), baseK + gb + (size_t)row*512 + cb);
            }
        }
        if (j <= 127) {
            uint32_t dst = sb + SM_V + (j&1)*16384;
            size_t gb = (size_t)j*16384;
            #pragma unroll
            for (int i = 0; i < 4; i++) {
                int id = i*256 + t;
                int row = id >> 5, cb = (id & 31) * 16;
                CPA16(dst + kswz(row, cb), baseV + gb + (size_t)row*512 + cb);
            }
        }
        CPCOMMIT();

        // mask prefetch for tile j
        int2 mA0, mA1, mB0, mB1;
        if (j < 128) {
            const int* mrow = mask + (size_t)(b*Nn + q0 + 16*r + g)*Nn + j*32 + 16*cw + 2*tq;
            mA0 = *(const int2*)mrow;
            mA1 = *(const int2*)(mrow + 8);
            mB0 = *(const int2*)(mrow + 8*(size_t)Nn);
            mB1 = *(const int2*)(mrow + 8*(size_t)Nn + 8);
        }

        float sA[4] = {}, sB[4] = {}, sC[4] = {}, sD[4] = {};

        if (j >= 1 && j < 128) {
            // ---- fused: S(j) interleaved with PV(j-1) at MMA granularity ----
            uint32_t sK = sb + SM_K + (j&1)*16384;
            uint32_t sV = sb + SM_V + ((j-1)&1)*16384;
            uint32_t pbuf = sb + SM_P + ((j-1)&1)*8192;
            uint32_t aph[4];
            #pragma unroll
            for (int ks = 0; ks < 16; ks++) {
                uint32_t bk[4];
                ldsm4(bk, sK + kswz(key, ks*32 + kb16));
                if (ks & 1) { mma16816h(sC, qf[ks], bk); mma16816h(sD, qf[ks], bk + 2); }
                else        { mma16816h(sA, qf[ks], bk); mma16816h(sB, qf[ks], bk + 2); }
                const int kc = ks >> 3, n2 = ks & 7;
                if (n2 == 0)
                    ldsm4(aph, pbuf + pswz(16*r + lrow, kc*32 + lk16));
                int vcb = (128*cw + n2*16 + (lane >> 4)*8) * 2;
                uint32_t bv[4];
                ldsm4t(bv, sV + kswz(kc*16 + vr, vcb));
                mma16816h(o[n2*2],   aph, bv);
                mma16816h(o[n2*2+1], aph, bv + 2);
            }
        } else if (j == 0) {
            // ---- S only ----
            uint32_t sK = sb + SM_K;
            #pragma unroll
            for (int ks = 0; ks < 16; ks++) {
                uint32_t bk[4];
                ldsm4(bk, sK + kswz(key, ks*32 + kb16));
                if (ks & 1) { mma16816h(sC, qf[ks], bk); mma16816h(sD, qf[ks], bk + 2); }
                else        { mma16816h(sA, qf[ks], bk); mma16816h(sB, qf[ks], bk + 2); }
            }
        } else {
            // ---- j == 128: PV only (tile 127) ----
            uint32_t sV = sb + SM_V + (127&1)*16384;
            uint32_t pbuf = sb + SM_P + (127&1)*8192;
            #pragma unroll
            for (int kc = 0; kc < 2; kc++) {
                uint32_t aph[4];
                ldsm4(aph, pbuf + pswz(16*r + lrow, kc*32 + lk16));
                #pragma unroll
                for (int n2 = 0; n2 < 8; n2++) {
                    int vcb = (128*cw + n2*16 + (lane >> 4)*8) * 2;
                    uint32_t bv[4];
                    ldsm4t(bv, sV + kswz(kc*16 + vr, vcb));
                    mma16816h(o[n2*2],   aph, bv);
                    mma16816h(o[n2*2+1], aph, bv + 2);
                }
            }
        }

        // ---- softmax + P store (tiles 0..127) ----
        if (j < 128) {
            const float sc = 0.0625f;
            float p00 = mA0.x ? __expf((sA[0]+sC[0])*sc) : 0.f;
            float p01 = mA0.y ? __expf((sA[1]+sC[1])*sc) : 0.f;
            float p02 = mB0.x ? __expf((sA[2]+sC[2])*sc) : 0.f;
            float p03 = mB0.y ? __expf((sA[3]+sC[3])*sc) : 0.f;
            float p10 = mA1.x ? __expf((sB[0]+sD[0])*sc) : 0.f;
            float p11 = mA1.y ? __expf((sB[1]+sD[1])*sc) : 0.f;
            float p12 = mB1.x ? __expf((sB[2]+sD[2])*sc) : 0.f;
            float p13 = mB1.y ? __expf((sB[3]+sD[3])*sc) : 0.f;
            l0 += p00 + p01 + p10 + p11;
            l1 += p02 + p03 + p12 + p13;
            char* pb = sm + SM_P + (j&1)*8192;
            int colb = (16*cw + 2*tq) * 2;
            int row0 = 16*r + g;
            #pragma unroll
            for (int nt = 0; nt < 2; nt++) {
                float pa = nt ? p10 : p00, pbv = nt ? p11 : p01;
                float pcv = nt ? p12 : p02, pd = nt ? p13 : p03;
                int cb2 = colb + nt*16;
                *(uint32_t*)(pb + pswz(row0,     cb2)) = packh2(pa, pbv);
                *(uint32_t*)(pb + pswz(row0 + 8, cb2)) = packh2(pcv, pd);
            }
        }
    }

    // ---- epilogue: l reduce (quad + col-warp pair), scale, store ----
    l0 += __shfl_xor_sync(0xffffffffu, l0, 1);
    l0 += __shfl_xor_sync(0xffffffffu, l0, 2);
    l1 += __shfl_xor_sync(0xffffffffu, l1, 1);
    l1 += __shfl_xor_sync(0xffffffffu, l1, 2);
    __syncthreads();                      // all PV done; K ring dead
    float* Ls = (float*)(sm + SM_K);
    if (tq == 0) {
        Ls[cw*64 + 16*r + g]     = l0;
        Ls[cw*64 + 16*r + 8 + g] = l1;
    }
    __syncthreads();
    float inv0 = 1.0f / (Ls[16*r + g]     + Ls[64 + 16*r + g]);
    float inv1 = 1.0f / (Ls[16*r + 8 + g] + Ls[64 + 16*r + 8 + g]);
    size_t row0 = (size_t)(b*Nn + q0 + 16*r + g);
    #pragma unroll
    for (int nt = 0; nt < 16; nt++) {
        int col = 128*cw + nt*8 + 2*tq;
        *(float2*)&out[row0*Dd + col]       = make_float2(o[nt][0]*inv0, o[nt][1]*inv0);
        *(float2*)&out[(row0 + 8)*Dd + col] = make_float2(o[nt][2]*inv1, o[nt][3]*inv1);
    }
}

extern "C" void kernel_launch(void* const* d_in, const int* in_sizes, int n_in,
                              void* d_out, int out_size)
{
    const float* x    = (const float*)d_in[0];
    const int*   mask = (const int*)  d_in[1];
    const float* Wq   = (const float*)d_in[2];
    const float* bq   = (const float*)d_in[3];
    const float* Wk   = (const float*)d_in[4];
    const float* bk   = (const float*)d_in[5];
    const float* Wv   = (const float*)d_in[6];
    const float* bv   = (const float*)d_in[7];
    float* out = (float*)d_out;

    cudaFuncSetAttribute(attn_kernel,
                         cudaFuncAttributeMaxDynamicSharedMemorySize, SM_TOT_A);
    cudaFuncSetAttribute(qkvmm_kernel,
                         cudaFuncAttributeMaxDynamicSharedMemorySize, SM_QKV_TOT);

    dim3 gM(3, Mm/128);
    qkvmm_kernel<<<gM, 256, SM_QKV_TOT>>>(x, Wq, Wk, Wv, bq, bk, bv);
    dim3 g2(Nn/64, Bb);
    attn_kernel<<<g2, 256, SM_TOT_A>>>(mask, out);
}